// round 2
// baseline (speedup 1.0000x reference)
#include <cuda_runtime.h>
#include <math.h>

#define T_SEQ 2048
#define NH 16
#define HD 64
#define C_EMB 1024
#define MTOT 4096  /* B*T */

// Scratch (allocation-free rule: __device__ globals)
__device__ float g_qkv[MTOT * 3 * C_EMB];   // 48 MB
__device__ float g_attn[MTOT * C_EMB];      // 16 MB
__device__ float g_mask[NH * T_SEQ];        // mask_pos * wave, per (h, rel)
__device__ int   g_cutoff[NH];              // rel >= cutoff -> mask == 0

__device__ __forceinline__ float sigmoidf_(float x) { return 1.f / (1.f + expf(-x)); }

// ---------------------------------------------------------------------------
// Prep: per-head span/period/ratio, 1-D mask table over rel, span_loss scalar.
// ---------------------------------------------------------------------------
__global__ void prep_kernel(const float* __restrict__ span_p,
                            const float* __restrict__ period_w,
                            const float* __restrict__ ratio_w,
                            float* loss_out)
{
    __shared__ float s_span[NH], s_period[NH], s_ratio[NH];
    int tid = threadIdx.x;
    if (tid < NH) {
        float span   = 2048.f * sigmoidf_(span_p[tid]);
        float period = 2.f + 2.f * sigmoidf_(period_w[tid]);
        float ratio  = -0.25f + 0.5f * sigmoidf_(ratio_w[tid]);
        s_span[tid] = span; s_period[tid] = period; s_ratio[tid] = ratio;
        int cut = (int)floorf(32.f + span) + 1;
        if (cut > T_SEQ) cut = T_SEQ;
        g_cutoff[tid] = cut;
    }
    __syncthreads();
    for (int idx = tid; idx < NH * T_SEQ; idx += blockDim.x) {
        int hh = idx >> 11, rel = idx & (T_SEQ - 1);
        float span = s_span[hh], period = s_period[hh], ratio = s_ratio[hh];
        float mp = (32.f - (float)rel + span) * (1.f / 32.f);
        mp = fminf(fmaxf(mp, 0.f), 1.f);
        float amp = period * 0.25f;
        float wave = 0.5f * (cosf(6.28318530717958647692f * (float)rel / period) + 1.f) * amp
                     + 0.5f + period * ratio;
        wave = fminf(fmaxf(wave, 0.f), 1.f);
        g_mask[idx] = mp * wave;
    }
    if (tid == 0 && loss_out) {
        float s = 0.f;
        for (int h = 0; h < NH; h++) {
            float lt = 1.f / s_period[h] + 2.f * s_ratio[h] - 0.25f + 0.5f;
            s += (s_span[h] + 32.f) * lt;
        }
        *loss_out = 2e-6f * s * (1.f / 16.f);
    }
}

// ---------------------------------------------------------------------------
// SGEMM: C[M,N] = A[M,K] @ B[K,N] + bias[N].  128x128x8 tile, 8x8/thread.
// M,N multiples of 128; K multiple of 8.
// ---------------------------------------------------------------------------
__global__ __launch_bounds__(256)
void sgemm_bias(const float* __restrict__ A, const float* __restrict__ B,
                const float* __restrict__ bias, float* __restrict__ C,
                int M, int N, int K)
{
    __shared__ float As[8][128];
    __shared__ float Bs[8][128];
    int tid = threadIdx.x;
    int tx = tid & 15, ty = tid >> 4;
    int bm = blockIdx.y << 7, bn = blockIdx.x << 7;
    int aRow = tid >> 1, aK = (tid & 1) << 2;
    int bK = tid >> 5, bCol = (tid & 31) << 2;
    const float* Ap = A + (bm + aRow) * K + aK;
    const float* Bp = B + bK * N + bn + bCol;

    float acc[8][8];
#pragma unroll
    for (int i = 0; i < 8; i++)
#pragma unroll
        for (int j = 0; j < 8; j++) acc[i][j] = 0.f;

    for (int k0 = 0; k0 < K; k0 += 8) {
        float4 av = *(const float4*)(Ap + k0);
        float4 bv = *(const float4*)(Bp + k0 * N);
        __syncthreads();
        As[aK + 0][aRow] = av.x; As[aK + 1][aRow] = av.y;
        As[aK + 2][aRow] = av.z; As[aK + 3][aRow] = av.w;
        *(float4*)&Bs[bK][bCol] = bv;
        __syncthreads();
#pragma unroll
        for (int kk = 0; kk < 8; kk++) {
            float4 a0 = *(const float4*)&As[kk][ty << 3];
            float4 a1 = *(const float4*)&As[kk][(ty << 3) + 4];
            float4 b0 = *(const float4*)&Bs[kk][tx << 3];
            float4 b1 = *(const float4*)&Bs[kk][(tx << 3) + 4];
            float ar[8] = {a0.x, a0.y, a0.z, a0.w, a1.x, a1.y, a1.z, a1.w};
            float br[8] = {b0.x, b0.y, b0.z, b0.w, b1.x, b1.y, b1.z, b1.w};
#pragma unroll
            for (int i = 0; i < 8; i++)
#pragma unroll
                for (int j = 0; j < 8; j++) acc[i][j] = fmaf(ar[i], br[j], acc[i][j]);
        }
    }
#pragma unroll
    for (int i = 0; i < 8; i++) {
        int row = bm + (ty << 3) + i;
#pragma unroll
        for (int j4 = 0; j4 < 2; j4++) {
            int col = bn + (tx << 3) + j4 * 4;
            float4 bz = *(const float4*)(bias + col);
            float4 o;
            o.x = acc[i][j4 * 4 + 0] + bz.x;
            o.y = acc[i][j4 * 4 + 1] + bz.y;
            o.z = acc[i][j4 * 4 + 2] + bz.z;
            o.w = acc[i][j4 * 4 + 3] + bz.w;
            *(float4*)(C + row * N + col) = o;
        }
    }
}

// ---------------------------------------------------------------------------
// Banded flash attention, fp32. One block = (b, h, 64 query rows).
// Online softmax; mask = g_mask[h][i-j]; tiles with rel >= cutoff skipped.
// ---------------------------------------------------------------------------
__global__ __launch_bounds__(256)
void attn_kernel(const float* __restrict__ qkv, float* __restrict__ yout)
{
    __shared__ float QsT[64 * 64];  // [d][i]
    __shared__ float KsT[64 * 64];  // [d][j]; reused as PsT [j][i]
    __shared__ float Vs[64 * 64];   // [j][d]

    int tid = threadIdx.x;
    int tx = tid & 15, ty = tid >> 4;
    int i0 = blockIdx.x << 6;
    int h = blockIdx.y, b = blockIdx.z;
    int baseq = h << 6;

#pragma unroll
    for (int it = 0; it < 4; it++) {
        int idx = tid + (it << 8);
        int il = idx >> 4, d4 = (idx & 15) << 2;
        float4 v = *(const float4*)(qkv + ((b * T_SEQ + i0 + il) * 3072 + baseq + d4));
        QsT[(d4 + 0) * 64 + il] = v.x; QsT[(d4 + 1) * 64 + il] = v.y;
        QsT[(d4 + 2) * 64 + il] = v.z; QsT[(d4 + 3) * 64 + il] = v.w;
    }

    float mrow[4], lrow[4], O[4][4];
#pragma unroll
    for (int r = 0; r < 4; r++) {
        mrow[r] = -1e30f; lrow[r] = 0.f;
#pragma unroll
        for (int c = 0; c < 4; c++) O[r][c] = 0.f;
    }

    int cutoff = g_cutoff[h];
    int t0 = i0 - cutoff + 1;
    int jstart = (t0 <= 0) ? 0 : (t0 & ~63);
    const float* maskh = g_mask + h * T_SEQ;

    for (int j0 = jstart; j0 <= i0; j0 += 64) {
        __syncthreads();
#pragma unroll
        for (int it = 0; it < 4; it++) {
            int idx = tid + (it << 8);
            int jl = idx >> 4, d4 = (idx & 15) << 2;
            const float* rowp = qkv + ((b * T_SEQ + j0 + jl) * 3072 + baseq + d4);
            float4 kv = *(const float4*)(rowp + 1024);
            KsT[(d4 + 0) * 64 + jl] = kv.x; KsT[(d4 + 1) * 64 + jl] = kv.y;
            KsT[(d4 + 2) * 64 + jl] = kv.z; KsT[(d4 + 3) * 64 + jl] = kv.w;
            float4 vv = *(const float4*)(rowp + 2048);
            *(float4*)&Vs[jl * 64 + d4] = vv;
        }
        __syncthreads();

        float s[4][4];
#pragma unroll
        for (int r = 0; r < 4; r++)
#pragma unroll
            for (int c = 0; c < 4; c++) s[r][c] = 0.f;
#pragma unroll 8
        for (int d = 0; d < 64; d++) {
            float4 q4 = *(const float4*)&QsT[d * 64 + (ty << 2)];
            float4 k4 = *(const float4*)&KsT[d * 64 + (tx << 2)];
            float qa[4] = {q4.x, q4.y, q4.z, q4.w};
            float ka[4] = {k4.x, k4.y, k4.z, k4.w};
#pragma unroll
            for (int r = 0; r < 4; r++)
#pragma unroll
                for (int c = 0; c < 4; c++) s[r][c] = fmaf(qa[r], ka[c], s[r][c]);
        }

#pragma unroll
        for (int r = 0; r < 4; r++) {
            int i = i0 + (ty << 2) + r;
            float sv[4]; float vmax = -1e30f;
#pragma unroll
            for (int c = 0; c < 4; c++) {
                int j = j0 + (tx << 2) + c;
                float x = s[r][c] * 0.125f;  // 1/sqrt(64)
                sv[c] = (j <= i) ? x : -1e30f;
                vmax = fmaxf(vmax, sv[c]);
            }
#pragma unroll
            for (int off = 8; off >= 1; off >>= 1)
                vmax = fmaxf(vmax, __shfl_xor_sync(0xffffffffu, vmax, off));
            float mnew = fmaxf(mrow[r], vmax);
            float f = __expf(mrow[r] - mnew);
            float rs = 0.f;
#pragma unroll
            for (int c = 0; c < 4; c++) {
                float p = 0.f;
                if (sv[c] > -1e29f) {
                    int rel = i - (j0 + (tx << 2) + c);
                    p = __expf(sv[c] - mnew) * __ldg(&maskh[rel]);
                }
                s[r][c] = p;  // reuse s as P storage
                rs += p;
            }
#pragma unroll
            for (int off = 8; off >= 1; off >>= 1)
                rs += __shfl_xor_sync(0xffffffffu, rs, off);
            lrow[r] = lrow[r] * f + rs;
            mrow[r] = mnew;
#pragma unroll
            for (int c = 0; c < 4; c++) O[r][c] *= f;
        }
        __syncthreads();  // done reading KsT
#pragma unroll
        for (int r = 0; r < 4; r++)
#pragma unroll
            for (int c = 0; c < 4; c++)
                KsT[((tx << 2) + c) * 64 + (ty << 2) + r] = s[r][c];  // PsT[j][i]
        __syncthreads();
#pragma unroll 8
        for (int j = 0; j < 64; j++) {
            float4 p4 = *(const float4*)&KsT[j * 64 + (ty << 2)];
            float4 v4 = *(const float4*)&Vs[j * 64 + (tx << 2)];
            float pa[4] = {p4.x, p4.y, p4.z, p4.w};
            float va[4] = {v4.x, v4.y, v4.z, v4.w};
#pragma unroll
            for (int r = 0; r < 4; r++)
#pragma unroll
                for (int c = 0; c < 4; c++) O[r][c] = fmaf(pa[r], va[c], O[r][c]);
        }
    }

#pragma unroll
    for (int r = 0; r < 4; r++) {
        float inv = 1.f / lrow[r];
        int i = i0 + (ty << 2) + r;
        float4 o;
        o.x = O[r][0] * inv; o.y = O[r][1] * inv;
        o.z = O[r][2] * inv; o.w = O[r][3] * inv;
        *(float4*)(yout + ((b * T_SEQ + i) * 1024 + baseq + (tx << 2))) = o;
    }
}

// ---------------------------------------------------------------------------
extern "C" void kernel_launch(void* const* d_in, const int* in_sizes, int n_in,
                              void* d_out, int out_size)
{
    const float* x        = (const float*)d_in[0];
    const float* w_attn   = (const float*)d_in[1];
    const float* b_attn   = (const float*)d_in[2];
    const float* w_proj   = (const float*)d_in[3];
    const float* b_proj   = (const float*)d_in[4];
    const float* span_p   = (const float*)d_in[5];
    const float* period_w = (const float*)d_in[6];
    const float* ratio_w  = (const float*)d_in[7];
    float* out = (float*)d_out;

    void* p;
    cudaGetSymbolAddress(&p, g_qkv);  float* qkv = (float*)p;
    cudaGetSymbolAddress(&p, g_attn); float* attn = (float*)p;

    float* loss_ptr = (out_size > MTOT * C_EMB) ? out + MTOT * C_EMB : nullptr;

    prep_kernel<<<1, 256>>>(span_p, period_w, ratio_w, loss_ptr);
    sgemm_bias<<<dim3(3 * C_EMB / 128, MTOT / 128), 256>>>(x, w_attn, b_attn, qkv,
                                                           MTOT, 3 * C_EMB, C_EMB);
    attn_kernel<<<dim3(T_SEQ / 64, NH, 2), 256>>>(qkv, attn);
    sgemm_bias<<<dim3(C_EMB / 128, MTOT / 128), 256>>>(attn, w_proj, b_proj, out,
                                                       MTOT, C_EMB, C_EMB);
}

// round 3
// speedup vs baseline: 1.0033x; 1.0033x over previous
#include <cuda_runtime.h>
#include <math.h>

#define T_SEQ 2048
#define NH 16
#define HD 64
#define C_EMB 1024
#define MTOT 4096  /* B*T */

// Scratch (allocation-free rule: __device__ globals)
__device__ float g_qkv[MTOT * 3 * C_EMB];   // 48 MB
__device__ float g_attn[MTOT * C_EMB];      // 16 MB
__device__ float g_mask[NH * T_SEQ];        // mask_pos * wave, per (h, rel)
__device__ int   g_cutoff[NH];              // rel >= cutoff -> mask == 0

__device__ __forceinline__ float sigmoidf_(float x) { return 1.f / (1.f + expf(-x)); }

// ---------------------------------------------------------------------------
// Prep: per-head span/period/ratio, 1-D mask table over rel, span_loss scalar.
// ---------------------------------------------------------------------------
__global__ void prep_kernel(const float* __restrict__ span_p,
                            const float* __restrict__ period_w,
                            const float* __restrict__ ratio_w,
                            float* loss_out)
{
    __shared__ float s_span[NH], s_period[NH], s_ratio[NH];
    int tid = threadIdx.x;
    if (tid < NH) {
        float span   = 2048.f * sigmoidf_(span_p[tid]);
        float period = 2.f + 2.f * sigmoidf_(period_w[tid]);
        float ratio  = -0.25f + 0.5f * sigmoidf_(ratio_w[tid]);
        s_span[tid] = span; s_period[tid] = period; s_ratio[tid] = ratio;
        int cut = (int)floorf(32.f + span) + 1;
        if (cut > T_SEQ) cut = T_SEQ;
        g_cutoff[tid] = cut;
    }
    __syncthreads();
    for (int idx = tid; idx < NH * T_SEQ; idx += blockDim.x) {
        int hh = idx >> 11, rel = idx & (T_SEQ - 1);
        float span = s_span[hh], period = s_period[hh], ratio = s_ratio[hh];
        float mp = (32.f - (float)rel + span) * (1.f / 32.f);
        mp = fminf(fmaxf(mp, 0.f), 1.f);
        float amp = period * 0.25f;
        float wave = 0.5f * (cosf(6.28318530717958647692f * (float)rel / period) + 1.f) * amp
                     + 0.5f + period * ratio;
        wave = fminf(fmaxf(wave, 0.f), 1.f);
        g_mask[idx] = mp * wave;
    }
    if (tid == 0 && loss_out) {
        float s = 0.f;
        for (int h = 0; h < NH; h++) {
            float lt = 1.f / s_period[h] + 2.f * s_ratio[h] - 0.25f + 0.5f;
            s += (s_span[h] + 32.f) * lt;
        }
        *loss_out = 2e-6f * s * (1.f / 16.f);
    }
}

// ---------------------------------------------------------------------------
// SGEMM: C[M,N] = A[M,K] @ B[K,N] + bias[N].  128x128x8 tile, 8x8/thread.
// M,N multiples of 128; K multiple of 8.
// ---------------------------------------------------------------------------
__global__ __launch_bounds__(256)
void sgemm_bias(const float* __restrict__ A, const float* __restrict__ B,
                const float* __restrict__ bias, float* __restrict__ C,
                int M, int N, int K)
{
    __shared__ float As[8][128];
    __shared__ float Bs[8][128];
    int tid = threadIdx.x;
    int tx = tid & 15, ty = tid >> 4;
    int bm = blockIdx.y << 7, bn = blockIdx.x << 7;
    int aRow = tid >> 1, aK = (tid & 1) << 2;
    int bK = tid >> 5, bCol = (tid & 31) << 2;
    const float* Ap = A + (bm + aRow) * K + aK;
    const float* Bp = B + bK * N + bn + bCol;

    float acc[8][8];
#pragma unroll
    for (int i = 0; i < 8; i++)
#pragma unroll
        for (int j = 0; j < 8; j++) acc[i][j] = 0.f;

    for (int k0 = 0; k0 < K; k0 += 8) {
        float4 av = *(const float4*)(Ap + k0);
        float4 bv = *(const float4*)(Bp + k0 * N);
        __syncthreads();
        As[aK + 0][aRow] = av.x; As[aK + 1][aRow] = av.y;
        As[aK + 2][aRow] = av.z; As[aK + 3][aRow] = av.w;
        *(float4*)&Bs[bK][bCol] = bv;
        __syncthreads();
#pragma unroll
        for (int kk = 0; kk < 8; kk++) {
            float4 a0 = *(const float4*)&As[kk][ty << 3];
            float4 a1 = *(const float4*)&As[kk][(ty << 3) + 4];
            float4 b0 = *(const float4*)&Bs[kk][tx << 3];
            float4 b1 = *(const float4*)&Bs[kk][(tx << 3) + 4];
            float ar[8] = {a0.x, a0.y, a0.z, a0.w, a1.x, a1.y, a1.z, a1.w};
            float br[8] = {b0.x, b0.y, b0.z, b0.w, b1.x, b1.y, b1.z, b1.w};
#pragma unroll
            for (int i = 0; i < 8; i++)
#pragma unroll
                for (int j = 0; j < 8; j++) acc[i][j] = fmaf(ar[i], br[j], acc[i][j]);
        }
    }
#pragma unroll
    for (int i = 0; i < 8; i++) {
        int row = bm + (ty << 3) + i;
#pragma unroll
        for (int j4 = 0; j4 < 2; j4++) {
            int col = bn + (tx << 3) + j4 * 4;
            float4 bz = *(const float4*)(bias + col);
            float4 o;
            o.x = acc[i][j4 * 4 + 0] + bz.x;
            o.y = acc[i][j4 * 4 + 1] + bz.y;
            o.z = acc[i][j4 * 4 + 2] + bz.z;
            o.w = acc[i][j4 * 4 + 3] + bz.w;
            *(float4*)(C + row * N + col) = o;
        }
    }
}

// ---------------------------------------------------------------------------
// Banded flash attention, fp32. One block = (b, h, 64 query rows).
// Online softmax; mask = g_mask[h][i-j]; tiles with rel >= cutoff skipped.
// ---------------------------------------------------------------------------
__global__ __launch_bounds__(256)
void attn_kernel(const float* __restrict__ qkv, float* __restrict__ yout)
{
    __shared__ float QsT[64 * 64];  // [d][i]
    __shared__ float KsT[64 * 64];  // [d][j]; reused as PsT [j][i]
    __shared__ float Vs[64 * 64];   // [j][d]

    int tid = threadIdx.x;
    int tx = tid & 15, ty = tid >> 4;
    int i0 = blockIdx.x << 6;
    int h = blockIdx.y, b = blockIdx.z;
    int baseq = h << 6;

#pragma unroll
    for (int it = 0; it < 4; it++) {
        int idx = tid + (it << 8);
        int il = idx >> 4, d4 = (idx & 15) << 2;
        float4 v = *(const float4*)(qkv + ((b * T_SEQ + i0 + il) * 3072 + baseq + d4));
        QsT[(d4 + 0) * 64 + il] = v.x; QsT[(d4 + 1) * 64 + il] = v.y;
        QsT[(d4 + 2) * 64 + il] = v.z; QsT[(d4 + 3) * 64 + il] = v.w;
    }

    float mrow[4], lrow[4], O[4][4];
#pragma unroll
    for (int r = 0; r < 4; r++) {
        mrow[r] = -1e30f; lrow[r] = 0.f;
#pragma unroll
        for (int c = 0; c < 4; c++) O[r][c] = 0.f;
    }

    int cutoff = g_cutoff[h];
    int t0 = i0 - cutoff + 1;
    int jstart = (t0 <= 0) ? 0 : (t0 & ~63);
    const float* maskh = g_mask + h * T_SEQ;

    for (int j0 = jstart; j0 <= i0; j0 += 64) {
        __syncthreads();
#pragma unroll
        for (int it = 0; it < 4; it++) {
            int idx = tid + (it << 8);
            int jl = idx >> 4, d4 = (idx & 15) << 2;
            const float* rowp = qkv + ((b * T_SEQ + j0 + jl) * 3072 + baseq + d4);
            float4 kv = *(const float4*)(rowp + 1024);
            KsT[(d4 + 0) * 64 + jl] = kv.x; KsT[(d4 + 1) * 64 + jl] = kv.y;
            KsT[(d4 + 2) * 64 + jl] = kv.z; KsT[(d4 + 3) * 64 + jl] = kv.w;
            float4 vv = *(const float4*)(rowp + 2048);
            *(float4*)&Vs[jl * 64 + d4] = vv;
        }
        __syncthreads();

        float s[4][4];
#pragma unroll
        for (int r = 0; r < 4; r++)
#pragma unroll
            for (int c = 0; c < 4; c++) s[r][c] = 0.f;
#pragma unroll 8
        for (int d = 0; d < 64; d++) {
            float4 q4 = *(const float4*)&QsT[d * 64 + (ty << 2)];
            float4 k4 = *(const float4*)&KsT[d * 64 + (tx << 2)];
            float qa[4] = {q4.x, q4.y, q4.z, q4.w};
            float ka[4] = {k4.x, k4.y, k4.z, k4.w};
#pragma unroll
            for (int r = 0; r < 4; r++)
#pragma unroll
                for (int c = 0; c < 4; c++) s[r][c] = fmaf(qa[r], ka[c], s[r][c]);
        }

#pragma unroll
        for (int r = 0; r < 4; r++) {
            int i = i0 + (ty << 2) + r;
            float sv[4]; float vmax = -1e30f;
#pragma unroll
            for (int c = 0; c < 4; c++) {
                int j = j0 + (tx << 2) + c;
                float x = s[r][c] * 0.125f;  // 1/sqrt(64)
                sv[c] = (j <= i) ? x : -1e30f;
                vmax = fmaxf(vmax, sv[c]);
            }
#pragma unroll
            for (int off = 8; off >= 1; off >>= 1)
                vmax = fmaxf(vmax, __shfl_xor_sync(0xffffffffu, vmax, off));
            float mnew = fmaxf(mrow[r], vmax);
            float f = __expf(mrow[r] - mnew);
            float rs = 0.f;
#pragma unroll
            for (int c = 0; c < 4; c++) {
                float p = 0.f;
                if (sv[c] > -1e29f) {
                    int rel = i - (j0 + (tx << 2) + c);
                    p = __expf(sv[c] - mnew) * __ldg(&maskh[rel]);
                }
                s[r][c] = p;  // reuse s as P storage
                rs += p;
            }
#pragma unroll
            for (int off = 8; off >= 1; off >>= 1)
                rs += __shfl_xor_sync(0xffffffffu, rs, off);
            lrow[r] = lrow[r] * f + rs;
            mrow[r] = mnew;
#pragma unroll
            for (int c = 0; c < 4; c++) O[r][c] *= f;
        }
        __syncthreads();  // done reading KsT
#pragma unroll
        for (int r = 0; r < 4; r++)
#pragma unroll
            for (int c = 0; c < 4; c++)
                KsT[((tx << 2) + c) * 64 + (ty << 2) + r] = s[r][c];  // PsT[j][i]
        __syncthreads();
#pragma unroll 8
        for (int j = 0; j < 64; j++) {
            float4 p4 = *(const float4*)&KsT[j * 64 + (ty << 2)];
            float4 v4 = *(const float4*)&Vs[j * 64 + (tx << 2)];
            float pa[4] = {p4.x, p4.y, p4.z, p4.w};
            float va[4] = {v4.x, v4.y, v4.z, v4.w};
#pragma unroll
            for (int r = 0; r < 4; r++)
#pragma unroll
                for (int c = 0; c < 4; c++) O[r][c] = fmaf(pa[r], va[c], O[r][c]);
        }
    }

#pragma unroll
    for (int r = 0; r < 4; r++) {
        float inv = 1.f / lrow[r];
        int i = i0 + (ty << 2) + r;
        float4 o;
        o.x = O[r][0] * inv; o.y = O[r][1] * inv;
        o.z = O[r][2] * inv; o.w = O[r][3] * inv;
        *(float4*)(yout + ((b * T_SEQ + i) * 1024 + baseq + (tx << 2))) = o;
    }
}

// ---------------------------------------------------------------------------
extern "C" void kernel_launch(void* const* d_in, const int* in_sizes, int n_in,
                              void* d_out, int out_size)
{
    const float* x        = (const float*)d_in[0];
    const float* w_attn   = (const float*)d_in[1];
    const float* b_attn   = (const float*)d_in[2];
    const float* w_proj   = (const float*)d_in[3];
    const float* b_proj   = (const float*)d_in[4];
    const float* span_p   = (const float*)d_in[5];
    const float* period_w = (const float*)d_in[6];
    const float* ratio_w  = (const float*)d_in[7];
    float* out = (float*)d_out;

    void* p;
    cudaGetSymbolAddress(&p, g_qkv);  float* qkv = (float*)p;
    cudaGetSymbolAddress(&p, g_attn); float* attn = (float*)p;

    float* loss_ptr = (out_size > MTOT * C_EMB) ? out + MTOT * C_EMB : nullptr;

    prep_kernel<<<1, 256>>>(span_p, period_w, ratio_w, loss_ptr);
    sgemm_bias<<<dim3(3 * C_EMB / 128, MTOT / 128), 256>>>(x, w_attn, b_attn, qkv,
                                                           MTOT, 3 * C_EMB, C_EMB);
    attn_kernel<<<dim3(T_SEQ / 64, NH, 2), 256>>>(qkv, attn);
    sgemm_bias<<<dim3(C_EMB / 128, MTOT / 128), 256>>>(attn, w_proj, b_proj, out,
                                                       MTOT, C_EMB, C_EMB);
}

// round 4
// speedup vs baseline: 1.5979x; 1.5926x over previous
#include <cuda_runtime.h>
#include <math.h>

#define T_SEQ 2048
#define NH 16
#define HD 64
#define C_EMB 1024
#define MTOT 4096  /* B*T */

// Scratch (allocation-free rule: __device__ globals)
__device__ float g_qkv[MTOT * 3 * C_EMB];   // 48 MB
__device__ float g_attn[MTOT * C_EMB];      // 16 MB
__device__ float g_mask[NH * T_SEQ];        // mask_pos * wave, per (h, rel)
__device__ int   g_cutoff[NH];              // rel >= cutoff -> mask == 0

__device__ __forceinline__ float sigmoidf_(float x) { return 1.f / (1.f + expf(-x)); }

__device__ __forceinline__ unsigned f2tf32(float x) {
    unsigned r;
    asm("cvt.rna.tf32.f32 %0, %1;" : "=r"(r) : "f"(x));
    return r;
}

__device__ __forceinline__ void cp16(void* smem, const void* g) {
    unsigned s = (unsigned)__cvta_generic_to_shared(smem);
    asm volatile("cp.async.cg.shared.global [%0], [%1], 16;" :: "r"(s), "l"(g));
}
__device__ __forceinline__ void cp_commit() { asm volatile("cp.async.commit_group;"); }
__device__ __forceinline__ void cp_wait0()  { asm volatile("cp.async.wait_group 0;"); }

__device__ __forceinline__ void mma_tf32(float c[4], unsigned a0, unsigned a1,
                                         unsigned a2, unsigned a3,
                                         unsigned b0, unsigned b1) {
    asm volatile(
        "mma.sync.aligned.m16n8k8.row.col.f32.tf32.tf32.f32 "
        "{%0,%1,%2,%3}, {%4,%5,%6,%7}, {%8,%9}, {%0,%1,%2,%3};"
        : "+f"(c[0]), "+f"(c[1]), "+f"(c[2]), "+f"(c[3])
        : "r"(a0), "r"(a1), "r"(a2), "r"(a3), "r"(b0), "r"(b1));
}

// ---------------------------------------------------------------------------
// Prep: per-head span/period/ratio, 1-D mask table over rel, span_loss scalar.
// ---------------------------------------------------------------------------
__global__ void prep_kernel(const float* __restrict__ span_p,
                            const float* __restrict__ period_w,
                            const float* __restrict__ ratio_w,
                            float* loss_out)
{
    __shared__ float s_span[NH], s_period[NH], s_ratio[NH];
    int tid = threadIdx.x;
    if (tid < NH) {
        float span   = 2048.f * sigmoidf_(span_p[tid]);
        float period = 2.f + 2.f * sigmoidf_(period_w[tid]);
        float ratio  = -0.25f + 0.5f * sigmoidf_(ratio_w[tid]);
        s_span[tid] = span; s_period[tid] = period; s_ratio[tid] = ratio;
        int cut = (int)floorf(32.f + span) + 1;
        if (cut > T_SEQ) cut = T_SEQ;
        g_cutoff[tid] = cut;
    }
    __syncthreads();
    for (int idx = tid; idx < NH * T_SEQ; idx += blockDim.x) {
        int hh = idx >> 11, rel = idx & (T_SEQ - 1);
        float span = s_span[hh], period = s_period[hh], ratio = s_ratio[hh];
        float mp = (32.f - (float)rel + span) * (1.f / 32.f);
        mp = fminf(fmaxf(mp, 0.f), 1.f);
        float amp = period * 0.25f;
        float wave = 0.5f * (cosf(6.28318530717958647692f * (float)rel / period) + 1.f) * amp
                     + 0.5f + period * ratio;
        wave = fminf(fmaxf(wave, 0.f), 1.f);
        g_mask[idx] = mp * wave;
    }
    if (tid == 0 && loss_out) {
        float s = 0.f;
        for (int h = 0; h < NH; h++) {
            float lt = 1.f / s_period[h] + 2.f * s_ratio[h] - 0.25f + 0.5f;
            s += (s_span[h] + 32.f) * lt;
        }
        *loss_out = 2e-6f * s * (1.f / 16.f);
    }
}

// ---------------------------------------------------------------------------
// TF32 tensor-core GEMM: C[M,N] = A[M,K] @ B[K,N] + bias[N]
// 128x128 CTA tile, BK=16, 8 warps (2x4), 64x32 warp tile, m16n8k8 mma,
// cp.async double-buffered shared staging. M%128==0, N%128==0, K%16==0.
// ---------------------------------------------------------------------------
__global__ __launch_bounds__(256)
void sgemm_tf32(const float* __restrict__ A, const float* __restrict__ B,
                const float* __restrict__ bias, float* __restrict__ C,
                int M, int N, int K)
{
    __shared__ float As[2][128][20];   // padded: conflict-free frag reads
    __shared__ float Bs[2][16][136];   // padded: conflict-free frag reads

    int tid  = threadIdx.x;
    int wid  = tid >> 5, lane = tid & 31;
    int gro  = lane >> 2;        // group id  (0..7)
    int tig  = lane & 3;         // thread-in-group (0..3)
    int wm   = (wid >> 2) << 6;  // 0 / 64
    int wn   = (wid & 3) << 5;   // 0 / 32 / 64 / 96
    int bm   = blockIdx.y << 7;
    int bn   = blockIdx.x << 7;

    // cp.async source/dest decomposition (2 x 16B chunks per thread per tile)
    int aRow0 = tid >> 1;                  // + it*128
    int aKc   = (tid & 1) << 3;            // 0 or 8 -> two 16B at +0,+4? no: see below
    // A tile: 128 rows x 16 floats = 512 chunks of 16B -> 2 per thread
    // chunk id = tid + it*256: row = id>>2, kc = (id&3)*4
    // B tile: 16 rows x 128 floats = 512 chunks -> row = id>>5, nc = (id&31)*4
    (void)aRow0; (void)aKc;

    float acc[4][4][4];
#pragma unroll
    for (int mt = 0; mt < 4; mt++)
#pragma unroll
        for (int nt = 0; nt < 4; nt++)
#pragma unroll
            for (int e = 0; e < 4; e++) acc[mt][nt][e] = 0.f;

    int nk = K >> 4;

    // prefetch stage 0
    {
#pragma unroll
        for (int it = 0; it < 2; it++) {
            int id = tid + (it << 8);
            int r = id >> 2, kc = (id & 3) << 2;
            cp16(&As[0][r][kc], A + (bm + r) * K + kc);
            int br = id >> 5, nc = (id & 31) << 2;
            cp16(&Bs[0][br][nc], B + br * N + bn + nc);
        }
        cp_commit();
    }

    int buf = 0;
    for (int k0 = 0; k0 < nk; k0++) {
        cp_wait0();
        __syncthreads();
        if (k0 + 1 < nk) {
            int kg = (k0 + 1) << 4;
#pragma unroll
            for (int it = 0; it < 2; it++) {
                int id = tid + (it << 8);
                int r = id >> 2, kc = (id & 3) << 2;
                cp16(&As[buf ^ 1][r][kc], A + (bm + r) * K + kg + kc);
                int br = id >> 5, nc = (id & 31) << 2;
                cp16(&Bs[buf ^ 1][br][nc], B + (kg + br) * N + bn + nc);
            }
            cp_commit();
        }

#pragma unroll
        for (int ks = 0; ks < 2; ks++) {
            unsigned af[4][4];
#pragma unroll
            for (int mt = 0; mt < 4; mt++) {
                int rb = wm + (mt << 4) + gro;
                int kc = (ks << 3) + tig;
                af[mt][0] = f2tf32(As[buf][rb][kc]);
                af[mt][1] = f2tf32(As[buf][rb + 8][kc]);
                af[mt][2] = f2tf32(As[buf][rb][kc + 4]);
                af[mt][3] = f2tf32(As[buf][rb + 8][kc + 4]);
            }
            unsigned bf[4][2];
#pragma unroll
            for (int nt = 0; nt < 4; nt++) {
                int nb = wn + (nt << 3) + gro;
                int kr = (ks << 3) + tig;
                bf[nt][0] = f2tf32(Bs[buf][kr][nb]);
                bf[nt][1] = f2tf32(Bs[buf][kr + 4][nb]);
            }
#pragma unroll
            for (int mt = 0; mt < 4; mt++)
#pragma unroll
                for (int nt = 0; nt < 4; nt++)
                    mma_tf32(acc[mt][nt], af[mt][0], af[mt][1], af[mt][2], af[mt][3],
                             bf[nt][0], bf[nt][1]);
        }
        __syncthreads();
        buf ^= 1;
    }

    // epilogue: add bias, store float2 pairs
#pragma unroll
    for (int mt = 0; mt < 4; mt++) {
        int row = bm + wm + (mt << 4) + gro;
#pragma unroll
        for (int nt = 0; nt < 4; nt++) {
            int col = bn + wn + (nt << 3) + (tig << 1);
            float2 bz = *(const float2*)(bias + col);
            float2 o0, o1;
            o0.x = acc[mt][nt][0] + bz.x; o0.y = acc[mt][nt][1] + bz.y;
            o1.x = acc[mt][nt][2] + bz.x; o1.y = acc[mt][nt][3] + bz.y;
            *(float2*)(C + row * N + col)       = o0;
            *(float2*)(C + (row + 8) * N + col) = o1;
        }
    }
}

// ---------------------------------------------------------------------------
// Banded flash attention, fp32. One block = (b, h, 64 query rows).
// Online softmax; mask = g_mask[h][i-j]; tiles with rel >= cutoff skipped.
// ---------------------------------------------------------------------------
__global__ __launch_bounds__(256)
void attn_kernel(const float* __restrict__ qkv, float* __restrict__ yout)
{
    __shared__ float QsT[64 * 64];  // [d][i]
    __shared__ float KsT[64 * 64];  // [d][j]; reused as PsT [j][i]
    __shared__ float Vs[64 * 64];   // [j][d]

    int tid = threadIdx.x;
    int tx = tid & 15, ty = tid >> 4;
    int i0 = blockIdx.x << 6;
    int h = blockIdx.y, b = blockIdx.z;
    int baseq = h << 6;

#pragma unroll
    for (int it = 0; it < 4; it++) {
        int idx = tid + (it << 8);
        int il = idx >> 4, d4 = (idx & 15) << 2;
        float4 v = *(const float4*)(qkv + ((b * T_SEQ + i0 + il) * 3072 + baseq + d4));
        QsT[(d4 + 0) * 64 + il] = v.x; QsT[(d4 + 1) * 64 + il] = v.y;
        QsT[(d4 + 2) * 64 + il] = v.z; QsT[(d4 + 3) * 64 + il] = v.w;
    }

    float mrow[4], lrow[4], O[4][4];
#pragma unroll
    for (int r = 0; r < 4; r++) {
        mrow[r] = -1e30f; lrow[r] = 0.f;
#pragma unroll
        for (int c = 0; c < 4; c++) O[r][c] = 0.f;
    }

    int cutoff = g_cutoff[h];
    int t0 = i0 - cutoff + 1;
    int jstart = (t0 <= 0) ? 0 : (t0 & ~63);
    const float* maskh = g_mask + h * T_SEQ;

    for (int j0 = jstart; j0 <= i0; j0 += 64) {
        __syncthreads();
#pragma unroll
        for (int it = 0; it < 4; it++) {
            int idx = tid + (it << 8);
            int jl = idx >> 4, d4 = (idx & 15) << 2;
            const float* rowp = qkv + ((b * T_SEQ + j0 + jl) * 3072 + baseq + d4);
            float4 kv = *(const float4*)(rowp + 1024);
            KsT[(d4 + 0) * 64 + jl] = kv.x; KsT[(d4 + 1) * 64 + jl] = kv.y;
            KsT[(d4 + 2) * 64 + jl] = kv.z; KsT[(d4 + 3) * 64 + jl] = kv.w;
            float4 vv = *(const float4*)(rowp + 2048);
            *(float4*)&Vs[jl * 64 + d4] = vv;
        }
        __syncthreads();

        float s[4][4];
#pragma unroll
        for (int r = 0; r < 4; r++)
#pragma unroll
            for (int c = 0; c < 4; c++) s[r][c] = 0.f;
#pragma unroll 8
        for (int d = 0; d < 64; d++) {
            float4 q4 = *(const float4*)&QsT[d * 64 + (ty << 2)];
            float4 k4 = *(const float4*)&KsT[d * 64 + (tx << 2)];
            float qa[4] = {q4.x, q4.y, q4.z, q4.w};
            float ka[4] = {k4.x, k4.y, k4.z, k4.w};
#pragma unroll
            for (int r = 0; r < 4; r++)
#pragma unroll
                for (int c = 0; c < 4; c++) s[r][c] = fmaf(qa[r], ka[c], s[r][c]);
        }

#pragma unroll
        for (int r = 0; r < 4; r++) {
            int i = i0 + (ty << 2) + r;
            float sv[4]; float vmax = -1e30f;
#pragma unroll
            for (int c = 0; c < 4; c++) {
                int j = j0 + (tx << 2) + c;
                float x = s[r][c] * 0.125f;  // 1/sqrt(64)
                sv[c] = (j <= i) ? x : -1e30f;
                vmax = fmaxf(vmax, sv[c]);
            }
#pragma unroll
            for (int off = 8; off >= 1; off >>= 1)
                vmax = fmaxf(vmax, __shfl_xor_sync(0xffffffffu, vmax, off));
            float mnew = fmaxf(mrow[r], vmax);
            float f = __expf(mrow[r] - mnew);
            float rs = 0.f;
#pragma unroll
            for (int c = 0; c < 4; c++) {
                float p = 0.f;
                if (sv[c] > -1e29f) {
                    int rel = i - (j0 + (tx << 2) + c);
                    p = __expf(sv[c] - mnew) * __ldg(&maskh[rel]);
                }
                s[r][c] = p;  // reuse s as P storage
                rs += p;
            }
#pragma unroll
            for (int off = 8; off >= 1; off >>= 1)
                rs += __shfl_xor_sync(0xffffffffu, rs, off);
            lrow[r] = lrow[r] * f + rs;
            mrow[r] = mnew;
#pragma unroll
            for (int c = 0; c < 4; c++) O[r][c] *= f;
        }
        __syncthreads();  // done reading KsT
#pragma unroll
        for (int r = 0; r < 4; r++)
#pragma unroll
            for (int c = 0; c < 4; c++)
                KsT[((tx << 2) + c) * 64 + (ty << 2) + r] = s[r][c];  // PsT[j][i]
        __syncthreads();
#pragma unroll 8
        for (int j = 0; j < 64; j++) {
            float4 p4 = *(const float4*)&KsT[j * 64 + (ty << 2)];
            float4 v4 = *(const float4*)&Vs[j * 64 + (tx << 2)];
            float pa[4] = {p4.x, p4.y, p4.z, p4.w};
            float va[4] = {v4.x, v4.y, v4.z, v4.w};
#pragma unroll
            for (int r = 0; r < 4; r++)
#pragma unroll
                for (int c = 0; c < 4; c++) O[r][c] = fmaf(pa[r], va[c], O[r][c]);
        }
    }

#pragma unroll
    for (int r = 0; r < 4; r++) {
        float inv = 1.f / lrow[r];
        int i = i0 + (ty << 2) + r;
        float4 o;
        o.x = O[r][0] * inv; o.y = O[r][1] * inv;
        o.z = O[r][2] * inv; o.w = O[r][3] * inv;
        *(float4*)(yout + ((b * T_SEQ + i) * 1024 + baseq + (tx << 2))) = o;
    }
}

// ---------------------------------------------------------------------------
extern "C" void kernel_launch(void* const* d_in, const int* in_sizes, int n_in,
                              void* d_out, int out_size)
{
    const float* x        = (const float*)d_in[0];
    const float* w_attn   = (const float*)d_in[1];
    const float* b_attn   = (const float*)d_in[2];
    const float* w_proj   = (const float*)d_in[3];
    const float* b_proj   = (const float*)d_in[4];
    const float* span_p   = (const float*)d_in[5];
    const float* period_w = (const float*)d_in[6];
    const float* ratio_w  = (const float*)d_in[7];
    float* out = (float*)d_out;

    void* p;
    cudaGetSymbolAddress(&p, g_qkv);  float* qkv = (float*)p;
    cudaGetSymbolAddress(&p, g_attn); float* attn = (float*)p;

    float* loss_ptr = (out_size > MTOT * C_EMB) ? out + MTOT * C_EMB : nullptr;

    prep_kernel<<<1, 256>>>(span_p, period_w, ratio_w, loss_ptr);
    sgemm_tf32<<<dim3(3 * C_EMB / 128, MTOT / 128), 256>>>(x, w_attn, b_attn, qkv,
                                                           MTOT, 3 * C_EMB, C_EMB);
    attn_kernel<<<dim3(T_SEQ / 64, NH, 2), 256>>>(qkv, attn);
    sgemm_tf32<<<dim3(C_EMB / 128, MTOT / 128), 256>>>(attn, w_proj, b_proj, out,
                                                       MTOT, C_EMB, C_EMB);
}

// round 7
// speedup vs baseline: 2.8131x; 1.7605x over previous
#include <cuda_runtime.h>
#include <math.h>

#define T_SEQ 2048
#define NH 16
#define HD 64
#define C_EMB 1024
#define MTOT 4096  /* B*T */

// Scratch (allocation-free rule: __device__ globals)
__device__ float g_qkv[MTOT * 3 * C_EMB];   // 48 MB
__device__ float g_attn[MTOT * C_EMB];      // 16 MB
__device__ float g_mask[NH * T_SEQ];        // mask_pos * wave, per (h, rel)
__device__ int   g_cutoff[NH];              // rel >= cutoff -> mask == 0

__device__ __forceinline__ float sigmoidf_(float x) { return 1.f / (1.f + expf(-x)); }

__device__ __forceinline__ unsigned f2tf32(float x) {
    unsigned r;
    asm("cvt.rna.tf32.f32 %0, %1;" : "=r"(r) : "f"(x));
    return r;
}

__device__ __forceinline__ void cp16(void* smem, const void* g) {
    unsigned s = (unsigned)__cvta_generic_to_shared(smem);
    asm volatile("cp.async.cg.shared.global [%0], [%1], 16;" :: "r"(s), "l"(g));
}
__device__ __forceinline__ void cp_commit() { asm volatile("cp.async.commit_group;"); }
__device__ __forceinline__ void cp_wait0()  { asm volatile("cp.async.wait_group 0;"); }

__device__ __forceinline__ void mma_tf32(float c[4], unsigned a0, unsigned a1,
                                         unsigned a2, unsigned a3,
                                         unsigned b0, unsigned b1) {
    asm volatile(
        "mma.sync.aligned.m16n8k8.row.col.f32.tf32.tf32.f32 "
        "{%0,%1,%2,%3}, {%4,%5,%6,%7}, {%8,%9}, {%0,%1,%2,%3};"
        : "+f"(c[0]), "+f"(c[1]), "+f"(c[2]), "+f"(c[3])
        : "r"(a0), "r"(a1), "r"(a2), "r"(a3), "r"(b0), "r"(b1));
}

// ---------------------------------------------------------------------------
// Prep: per-head span/period/ratio, 1-D mask table over rel, span_loss scalar.
// ---------------------------------------------------------------------------
__global__ void prep_kernel(const float* __restrict__ span_p,
                            const float* __restrict__ period_w,
                            const float* __restrict__ ratio_w,
                            float* loss_out)
{
    __shared__ float s_span[NH], s_period[NH], s_ratio[NH];
    int tid = threadIdx.x;
    if (tid < NH) {
        float span   = 2048.f * sigmoidf_(span_p[tid]);
        float period = 2.f + 2.f * sigmoidf_(period_w[tid]);
        float ratio  = -0.25f + 0.5f * sigmoidf_(ratio_w[tid]);
        s_span[tid] = span; s_period[tid] = period; s_ratio[tid] = ratio;
        int cut = (int)floorf(32.f + span) + 1;
        if (cut > T_SEQ) cut = T_SEQ;
        g_cutoff[tid] = cut;
    }
    __syncthreads();
    for (int idx = tid; idx < NH * T_SEQ; idx += blockDim.x) {
        int hh = idx >> 11, rel = idx & (T_SEQ - 1);
        float span = s_span[hh], period = s_period[hh], ratio = s_ratio[hh];
        float mp = (32.f - (float)rel + span) * (1.f / 32.f);
        mp = fminf(fmaxf(mp, 0.f), 1.f);
        float amp = period * 0.25f;
        float wave = 0.5f * (cosf(6.28318530717958647692f * (float)rel / period) + 1.f) * amp
                     + 0.5f + period * ratio;
        wave = fminf(fmaxf(wave, 0.f), 1.f);
        g_mask[idx] = mp * wave;
    }
    if (tid == 0 && loss_out) {
        float s = 0.f;
        for (int h = 0; h < NH; h++) {
            float lt = 1.f / s_period[h] + 2.f * s_ratio[h] - 0.25f + 0.5f;
            s += (s_span[h] + 32.f) * lt;
        }
        *loss_out = 2e-6f * s * (1.f / 16.f);
    }
}

// ---------------------------------------------------------------------------
// TF32 tensor-core GEMM: C[M,N] = A[M,K] @ B[K,N] + bias[N]
// 128x128 CTA tile, BK=16, 8 warps, 64x32 warp tile, m16n8k8 mma,
// cp.async double-buffered. M%128==0, N%128==0, K%16==0.
// ---------------------------------------------------------------------------
__global__ __launch_bounds__(256)
void sgemm_tf32(const float* __restrict__ A, const float* __restrict__ B,
                const float* __restrict__ bias, float* __restrict__ C,
                int M, int N, int K)
{
    __shared__ float As[2][128][20];
    __shared__ float Bs[2][16][136];

    int tid  = threadIdx.x;
    int wid  = tid >> 5, lane = tid & 31;
    int gro  = lane >> 2;
    int tig  = lane & 3;
    int wm   = (wid >> 2) << 6;
    int wn   = (wid & 3) << 5;
    int bm   = blockIdx.y << 7;
    int bn   = blockIdx.x << 7;

    float acc[4][4][4];
#pragma unroll
    for (int mt = 0; mt < 4; mt++)
#pragma unroll
        for (int nt = 0; nt < 4; nt++)
#pragma unroll
            for (int e = 0; e < 4; e++) acc[mt][nt][e] = 0.f;

    int nk = K >> 4;

    {
#pragma unroll
        for (int it = 0; it < 2; it++) {
            int id = tid + (it << 8);
            int r = id >> 2, kc = (id & 3) << 2;
            cp16(&As[0][r][kc], A + (bm + r) * K + kc);
            int br = id >> 5, nc = (id & 31) << 2;
            cp16(&Bs[0][br][nc], B + br * N + bn + nc);
        }
        cp_commit();
    }

    int buf = 0;
    for (int k0 = 0; k0 < nk; k0++) {
        cp_wait0();
        __syncthreads();
        if (k0 + 1 < nk) {
            int kg = (k0 + 1) << 4;
#pragma unroll
            for (int it = 0; it < 2; it++) {
                int id = tid + (it << 8);
                int r = id >> 2, kc = (id & 3) << 2;
                cp16(&As[buf ^ 1][r][kc], A + (bm + r) * K + kg + kc);
                int br = id >> 5, nc = (id & 31) << 2;
                cp16(&Bs[buf ^ 1][br][nc], B + (kg + br) * N + bn + nc);
            }
            cp_commit();
        }

#pragma unroll
        for (int ks = 0; ks < 2; ks++) {
            unsigned af[4][4];
#pragma unroll
            for (int mt = 0; mt < 4; mt++) {
                int rb = wm + (mt << 4) + gro;
                int kc = (ks << 3) + tig;
                af[mt][0] = f2tf32(As[buf][rb][kc]);
                af[mt][1] = f2tf32(As[buf][rb + 8][kc]);
                af[mt][2] = f2tf32(As[buf][rb][kc + 4]);
                af[mt][3] = f2tf32(As[buf][rb + 8][kc + 4]);
            }
            unsigned bf[4][2];
#pragma unroll
            for (int nt = 0; nt < 4; nt++) {
                int nb = wn + (nt << 3) + gro;
                int kr = (ks << 3) + tig;
                bf[nt][0] = f2tf32(Bs[buf][kr][nb]);
                bf[nt][1] = f2tf32(Bs[buf][kr + 4][nb]);
            }
#pragma unroll
            for (int mt = 0; mt < 4; mt++)
#pragma unroll
                for (int nt = 0; nt < 4; nt++)
                    mma_tf32(acc[mt][nt], af[mt][0], af[mt][1], af[mt][2], af[mt][3],
                             bf[nt][0], bf[nt][1]);
        }
        __syncthreads();
        buf ^= 1;
    }

#pragma unroll
    for (int mt = 0; mt < 4; mt++) {
        int row = bm + wm + (mt << 4) + gro;
#pragma unroll
        for (int nt = 0; nt < 4; nt++) {
            int col = bn + wn + (nt << 3) + (tig << 1);
            float2 bz = *(const float2*)(bias + col);
            float2 o0, o1;
            o0.x = acc[mt][nt][0] + bz.x; o0.y = acc[mt][nt][1] + bz.y;
            o1.x = acc[mt][nt][2] + bz.x; o1.y = acc[mt][nt][3] + bz.y;
            *(float2*)(C + row * N + col)       = o0;
            *(float2*)(C + (row + 8) * N + col) = o1;
        }
    }
}

// ---------------------------------------------------------------------------
// Banded flash attention, tf32 tensor cores + fp32 softmax.
// Block = (b, h, 64 query rows), 4 warps, warp = 16 rows.
// Q lives in A-fragments (registers) for the whole block.
// P: mma C-layout -> A-layout via warp shuffles (no smem round-trip).
// ---------------------------------------------------------------------------
__global__ __launch_bounds__(128)
void attn_tc(const float* __restrict__ qkv, float* __restrict__ yout)
{
    __shared__ float Ks[64][68];  // [j][d]  pad 68: B-frag reads conflict-free
    __shared__ float Vs[64][72];  // [j][d]  pad 72: B-frag reads conflict-free

    int tid  = threadIdx.x;
    int wid  = tid >> 5, lane = tid & 31;
    int gro  = lane >> 2, tig = lane & 3;
    int i0   = blockIdx.x << 6;
    int h    = blockIdx.y, b = blockIdx.z;
    int baseq = h << 6;
    int wrow = wid << 4;
    int ir0 = i0 + wrow + gro;
    int ir1 = ir0 + 8;

    // ---- Q fragments (once per block) ----
    const float* qp = qkv + ((size_t)(b * T_SEQ + i0 + wrow)) * 3072 + baseq;
    unsigned qf[8][4];
#pragma unroll
    for (int kt = 0; kt < 8; kt++) {
        int kc = (kt << 3) + tig;
        qf[kt][0] = f2tf32(qp[gro * 3072 + kc]);
        qf[kt][1] = f2tf32(qp[(gro + 8) * 3072 + kc]);
        qf[kt][2] = f2tf32(qp[gro * 3072 + kc + 4]);
        qf[kt][3] = f2tf32(qp[(gro + 8) * 3072 + kc + 4]);
    }

    float m0 = -1e30f, m1 = -1e30f, l0 = 0.f, l1 = 0.f;
    float oreg[8][4];
#pragma unroll
    for (int nt = 0; nt < 8; nt++)
#pragma unroll
        for (int e = 0; e < 4; e++) oreg[nt][e] = 0.f;

    int cutoff = g_cutoff[h];
    int t0 = i0 - cutoff + 1;
    int jstart = (t0 <= 0) ? 0 : (t0 & ~63);
    const float* maskh = g_mask + h * T_SEQ;

    int srcA = (lane & ~3) | (tig >> 1);
    int srcB = srcA + 2;
    bool odd = (tig & 1);

    for (int j0 = jstart; j0 <= i0; j0 += 64) {
        __syncthreads();   // prior-iteration LDS reads done before overwrite
#pragma unroll
        for (int it = 0; it < 8; it++) {
            int row = (tid >> 4) + (it << 3);
            int col = (tid & 15) << 2;
            const float* rp = qkv + ((size_t)(b * T_SEQ + j0 + row)) * 3072 + baseq + col;
            float4 kv = *(const float4*)(rp + 1024);
            *(float4*)&Ks[row][col] = kv;
            float4 vv = *(const float4*)(rp + 2048);
            *(float4*)&Vs[row][col] = vv;
        }
        __syncthreads();

        // ---- S = Q K^T  (16x64 per warp) ----
        float sreg[8][4];
#pragma unroll
        for (int nt = 0; nt < 8; nt++) {
#pragma unroll
            for (int e = 0; e < 4; e++) sreg[nt][e] = 0.f;
            int jb = (nt << 3) + gro;
#pragma unroll
            for (int kt = 0; kt < 8; kt++) {
                unsigned b0 = f2tf32(Ks[jb][(kt << 3) + tig]);
                unsigned b1 = f2tf32(Ks[jb][(kt << 3) + tig + 4]);
                mma_tf32(sreg[nt], qf[kt][0], qf[kt][1], qf[kt][2], qf[kt][3], b0, b1);
            }
        }

        // ---- online softmax (fp32, fragment-native) ----
        float vm0 = -1e30f, vm1 = -1e30f;
#pragma unroll
        for (int nt = 0; nt < 8; nt++) {
            int jn = j0 + (nt << 3) + (tig << 1);
            float s0 = (jn     <= ir0) ? sreg[nt][0] * 0.125f : -1e30f;
            float s1 = (jn + 1 <= ir0) ? sreg[nt][1] * 0.125f : -1e30f;
            float s2 = (jn     <= ir1) ? sreg[nt][2] * 0.125f : -1e30f;
            float s3 = (jn + 1 <= ir1) ? sreg[nt][3] * 0.125f : -1e30f;
            sreg[nt][0] = s0; sreg[nt][1] = s1; sreg[nt][2] = s2; sreg[nt][3] = s3;
            vm0 = fmaxf(vm0, fmaxf(s0, s1));
            vm1 = fmaxf(vm1, fmaxf(s2, s3));
        }
        vm0 = fmaxf(vm0, __shfl_xor_sync(0xffffffffu, vm0, 1));
        vm0 = fmaxf(vm0, __shfl_xor_sync(0xffffffffu, vm0, 2));
        vm1 = fmaxf(vm1, __shfl_xor_sync(0xffffffffu, vm1, 1));
        vm1 = fmaxf(vm1, __shfl_xor_sync(0xffffffffu, vm1, 2));
        float mn0 = fmaxf(m0, vm0), mn1 = fmaxf(m1, vm1);
        float f0 = __expf(m0 - mn0), f1 = __expf(m1 - mn1);
        float rs0 = 0.f, rs1 = 0.f;
#pragma unroll
        for (int nt = 0; nt < 8; nt++) {
            int jn = j0 + (nt << 3) + (tig << 1);
            float p0 = 0.f, p1 = 0.f, p2 = 0.f, p3 = 0.f;
            if (jn <= ir0) {
                int r = ir0 - jn; if (r > 2047) r = 2047;
                p0 = __expf(sreg[nt][0] - mn0) * __ldg(maskh + r);
            }
            if (jn + 1 <= ir0) {
                int r = ir0 - jn - 1; if (r > 2047) r = 2047;
                p1 = __expf(sreg[nt][1] - mn0) * __ldg(maskh + r);
            }
            if (jn <= ir1) {
                int r = ir1 - jn; if (r > 2047) r = 2047;
                p2 = __expf(sreg[nt][2] - mn1) * __ldg(maskh + r);
            }
            if (jn + 1 <= ir1) {
                int r = ir1 - jn - 1; if (r > 2047) r = 2047;
                p3 = __expf(sreg[nt][3] - mn1) * __ldg(maskh + r);
            }
            sreg[nt][0] = p0; sreg[nt][1] = p1; sreg[nt][2] = p2; sreg[nt][3] = p3;
            rs0 += p0 + p1; rs1 += p2 + p3;
        }
        rs0 += __shfl_xor_sync(0xffffffffu, rs0, 1);
        rs0 += __shfl_xor_sync(0xffffffffu, rs0, 2);
        rs1 += __shfl_xor_sync(0xffffffffu, rs1, 1);
        rs1 += __shfl_xor_sync(0xffffffffu, rs1, 2);
        l0 = l0 * f0 + rs0; m0 = mn0;
        l1 = l1 * f1 + rs1; m1 = mn1;
#pragma unroll
        for (int nt = 0; nt < 8; nt++) {
            oreg[nt][0] *= f0; oreg[nt][1] *= f0;
            oreg[nt][2] *= f1; oreg[nt][3] *= f1;
        }

        // ---- O += P V : P C-layout -> A-layout via shuffles ----
#pragma unroll
        for (int kt = 0; kt < 8; kt++) {
            float y0 = __shfl_sync(0xffffffffu, sreg[kt][0], srcA);
            float y1 = __shfl_sync(0xffffffffu, sreg[kt][1], srcA);
            float y2 = __shfl_sync(0xffffffffu, sreg[kt][2], srcA);
            float y3 = __shfl_sync(0xffffffffu, sreg[kt][3], srcA);
            float z0 = __shfl_sync(0xffffffffu, sreg[kt][0], srcB);
            float z1 = __shfl_sync(0xffffffffu, sreg[kt][1], srcB);
            float z2 = __shfl_sync(0xffffffffu, sreg[kt][2], srcB);
            float z3 = __shfl_sync(0xffffffffu, sreg[kt][3], srcB);
            unsigned a0 = f2tf32(odd ? y1 : y0);
            unsigned a1 = f2tf32(odd ? y3 : y2);
            unsigned a2 = f2tf32(odd ? z1 : z0);
            unsigned a3 = f2tf32(odd ? z3 : z2);
            int kb = kt << 3;
#pragma unroll
            for (int nt = 0; nt < 8; nt++) {
                unsigned b0 = f2tf32(Vs[kb + tig][(nt << 3) + gro]);
                unsigned b1 = f2tf32(Vs[kb + tig + 4][(nt << 3) + gro]);
                mma_tf32(oreg[nt], a0, a1, a2, a3, b0, b1);
            }
        }
    }

    // ---- epilogue ----
    float inv0 = 1.f / l0, inv1 = 1.f / l1;
#pragma unroll
    for (int nt = 0; nt < 8; nt++) {
        int col = baseq + (nt << 3) + (tig << 1);
        float2 o0, o1;
        o0.x = oreg[nt][0] * inv0; o0.y = oreg[nt][1] * inv0;
        o1.x = oreg[nt][2] * inv1; o1.y = oreg[nt][3] * inv1;
        *(float2*)(yout + ((size_t)(b * T_SEQ + ir0)) * 1024 + col) = o0;
        *(float2*)(yout + ((size_t)(b * T_SEQ + ir1)) * 1024 + col) = o1;
    }
}

// ---------------------------------------------------------------------------
extern "C" void kernel_launch(void* const* d_in, const int* in_sizes, int n_in,
                              void* d_out, int out_size)
{
    const float* x        = (const float*)d_in[0];
    const float* w_attn   = (const float*)d_in[1];
    const float* b_attn   = (const float*)d_in[2];
    const float* w_proj   = (const float*)d_in[3];
    const float* b_proj   = (const float*)d_in[4];
    const float* span_p   = (const float*)d_in[5];
    const float* period_w = (const float*)d_in[6];
    const float* ratio_w  = (const float*)d_in[7];
    float* out = (float*)d_out;

    void* p;
    cudaGetSymbolAddress(&p, g_qkv);  float* qkv = (float*)p;
    cudaGetSymbolAddress(&p, g_attn); float* attn = (float*)p;

    float* loss_ptr = (out_size > MTOT * C_EMB) ? out + MTOT * C_EMB : nullptr;

    prep_kernel<<<1, 256>>>(span_p, period_w, ratio_w, loss_ptr);
    sgemm_tf32<<<dim3(3 * C_EMB / 128, MTOT / 128), 256>>>(x, w_attn, b_attn, qkv,
                                                           MTOT, 3 * C_EMB, C_EMB);
    attn_tc<<<dim3(T_SEQ / 64, NH, 2), 128>>>(qkv, attn);
    sgemm_tf32<<<dim3(C_EMB / 128, MTOT / 128), 256>>>(attn, w_proj, b_proj, out,
                                                       MTOT, C_EMB, C_EMB);
}

// round 8
// speedup vs baseline: 3.2646x; 1.1605x over previous
#include <cuda_runtime.h>
#include <math.h>

#define T_SEQ 2048
#define NH 16
#define HD 64
#define C_EMB 1024
#define MTOT 4096  /* B*T */

// Scratch (allocation-free rule: __device__ globals)
__device__ float g_qkv[MTOT * 3 * C_EMB];   // 48 MB (tf32-rounded by GEMM1 epilogue)
__device__ float g_attn[MTOT * C_EMB];      // 16 MB (tf32-rounded by attn epilogue)
__device__ float g_xc[MTOT * C_EMB];        // 16 MB tf32-rounded x
__device__ float g_wac[C_EMB * 3 * C_EMB];  // 12 MB tf32-rounded w_attn
__device__ float g_wpc[C_EMB * C_EMB];      //  4 MB tf32-rounded w_proj
__device__ float g_mask[NH * T_SEQ];
__device__ int   g_cutoff[NH];

__device__ __forceinline__ float sigmoidf_(float x) { return 1.f / (1.f + expf(-x)); }

__device__ __forceinline__ unsigned f2tf32(float x) {
    unsigned r;
    asm("cvt.rna.tf32.f32 %0, %1;" : "=r"(r) : "f"(x));
    return r;
}

__device__ __forceinline__ void cp16(void* smem, const void* g) {
    unsigned s = (unsigned)__cvta_generic_to_shared(smem);
    asm volatile("cp.async.cg.shared.global [%0], [%1], 16;" :: "r"(s), "l"(g));
}
__device__ __forceinline__ void cp_commit() { asm volatile("cp.async.commit_group;"); }
__device__ __forceinline__ void cp_wait0()  { asm volatile("cp.async.wait_group 0;"); }

__device__ __forceinline__ void mma_tf32(float c[4], unsigned a0, unsigned a1,
                                         unsigned a2, unsigned a3,
                                         unsigned b0, unsigned b1) {
    asm volatile(
        "mma.sync.aligned.m16n8k8.row.col.f32.tf32.tf32.f32 "
        "{%0,%1,%2,%3}, {%4,%5,%6,%7}, {%8,%9}, {%0,%1,%2,%3};"
        : "+f"(c[0]), "+f"(c[1]), "+f"(c[2]), "+f"(c[3])
        : "r"(a0), "r"(a1), "r"(a2), "r"(a3), "r"(b0), "r"(b1));
}

// ---------------------------------------------------------------------------
// Elementwise tf32 rounding (rna), float4-vectorized. n4 = n/4.
// ---------------------------------------------------------------------------
__global__ void cvt_tf32_k(const float4* __restrict__ s, float4* __restrict__ d, int n4)
{
    int i = blockIdx.x * blockDim.x + threadIdx.x;
    if (i >= n4) return;
    float4 v = s[i];
    v.x = __uint_as_float(f2tf32(v.x));
    v.y = __uint_as_float(f2tf32(v.y));
    v.z = __uint_as_float(f2tf32(v.z));
    v.w = __uint_as_float(f2tf32(v.w));
    d[i] = v;
}

// ---------------------------------------------------------------------------
// Prep: per-head span/period/ratio, 1-D mask table over rel, span_loss scalar.
// ---------------------------------------------------------------------------
__global__ void prep_kernel(const float* __restrict__ span_p,
                            const float* __restrict__ period_w,
                            const float* __restrict__ ratio_w,
                            float* loss_out)
{
    __shared__ float s_span[NH], s_period[NH], s_ratio[NH];
    int tid = threadIdx.x;
    if (tid < NH) {
        float span   = 2048.f * sigmoidf_(span_p[tid]);
        float period = 2.f + 2.f * sigmoidf_(period_w[tid]);
        float ratio  = -0.25f + 0.5f * sigmoidf_(ratio_w[tid]);
        s_span[tid] = span; s_period[tid] = period; s_ratio[tid] = ratio;
        int cut = (int)floorf(32.f + span) + 1;
        if (cut > T_SEQ) cut = T_SEQ;
        g_cutoff[tid] = cut;
    }
    __syncthreads();
    for (int idx = tid; idx < NH * T_SEQ; idx += blockDim.x) {
        int hh = idx >> 11, rel = idx & (T_SEQ - 1);
        float span = s_span[hh], period = s_period[hh], ratio = s_ratio[hh];
        float mp = (32.f - (float)rel + span) * (1.f / 32.f);
        mp = fminf(fmaxf(mp, 0.f), 1.f);
        float amp = period * 0.25f;
        float wave = 0.5f * (cosf(6.28318530717958647692f * (float)rel / period) + 1.f) * amp
                     + 0.5f + period * ratio;
        wave = fminf(fmaxf(wave, 0.f), 1.f);
        g_mask[idx] = mp * wave;
    }
    if (tid == 0 && loss_out) {
        float s = 0.f;
        for (int h = 0; h < NH; h++) {
            float lt = 1.f / s_period[h] + 2.f * s_ratio[h] - 0.25f + 0.5f;
            s += (s_span[h] + 32.f) * lt;
        }
        *loss_out = 2e-6f * s * (1.f / 16.f);
    }
}

// ---------------------------------------------------------------------------
// TF32 tensor-core GEMM: C[M,N] = A[M,K] @ B[K,N] + bias[N]
// Inputs MUST be pre-rounded to tf32 bit patterns (no cvt in loop).
// 128x128 CTA, 4 warps, 64x64 warp tile, BK=16, cp.async double-buffered,
// one __syncthreads per K-tile. If ROUND, output is tf32-rounded.
// ---------------------------------------------------------------------------
template<bool ROUND>
__global__ __launch_bounds__(128)
void gemm_tf32(const float* __restrict__ A, const float* __restrict__ B,
               const float* __restrict__ bias, float* __restrict__ C,
               int M, int N, int K)
{
    __shared__ float As[2][128][20];
    __shared__ float Bs[2][16][136];

    int tid  = threadIdx.x;
    int wid  = tid >> 5, lane = tid & 31;
    int gro  = lane >> 2, tig = lane & 3;
    int wm   = (wid >> 1) << 6;   // 0/64
    int wn   = (wid & 1) << 6;    // 0/64
    int bm   = blockIdx.y << 7;
    int bn   = blockIdx.x << 7;

    float acc[4][8][4];
#pragma unroll
    for (int mt = 0; mt < 4; mt++)
#pragma unroll
        for (int nt = 0; nt < 8; nt++)
#pragma unroll
            for (int e = 0; e < 4; e++) acc[mt][nt][e] = 0.f;

    int nk = K >> 4;

#pragma unroll
    for (int it = 0; it < 4; it++) {
        int id = tid + (it << 7);
        int r = id >> 2, kc = (id & 3) << 2;
        cp16(&As[0][r][kc], A + (size_t)(bm + r) * K + kc);
        int br = id >> 5, nc = (id & 31) << 2;
        cp16(&Bs[0][br][nc], B + (size_t)br * N + bn + nc);
    }
    cp_commit();

    int buf = 0;
    for (int k0 = 0; k0 < nk; k0++) {
        cp_wait0();
        __syncthreads();
        if (k0 + 1 < nk) {
            int kg = (k0 + 1) << 4;
#pragma unroll
            for (int it = 0; it < 4; it++) {
                int id = tid + (it << 7);
                int r = id >> 2, kc = (id & 3) << 2;
                cp16(&As[buf ^ 1][r][kc], A + (size_t)(bm + r) * K + kg + kc);
                int br = id >> 5, nc = (id & 31) << 2;
                cp16(&Bs[buf ^ 1][br][nc], B + (size_t)(kg + br) * N + bn + nc);
            }
            cp_commit();
        }

#pragma unroll
        for (int ks = 0; ks < 2; ks++) {
            unsigned af[4][4];
#pragma unroll
            for (int mt = 0; mt < 4; mt++) {
                int rb = wm + (mt << 4) + gro;
                int kc = (ks << 3) + tig;
                af[mt][0] = __float_as_uint(As[buf][rb][kc]);
                af[mt][1] = __float_as_uint(As[buf][rb + 8][kc]);
                af[mt][2] = __float_as_uint(As[buf][rb][kc + 4]);
                af[mt][3] = __float_as_uint(As[buf][rb + 8][kc + 4]);
            }
            unsigned bf[8][2];
#pragma unroll
            for (int nt = 0; nt < 8; nt++) {
                int nb = wn + (nt << 3) + gro;
                int kr = (ks << 3) + tig;
                bf[nt][0] = __float_as_uint(Bs[buf][kr][nb]);
                bf[nt][1] = __float_as_uint(Bs[buf][kr + 4][nb]);
            }
#pragma unroll
            for (int mt = 0; mt < 4; mt++)
#pragma unroll
                for (int nt = 0; nt < 8; nt++)
                    mma_tf32(acc[mt][nt], af[mt][0], af[mt][1], af[mt][2], af[mt][3],
                             bf[nt][0], bf[nt][1]);
        }
        buf ^= 1;
    }

#pragma unroll
    for (int mt = 0; mt < 4; mt++) {
        int row = bm + wm + (mt << 4) + gro;
#pragma unroll
        for (int nt = 0; nt < 8; nt++) {
            int col = bn + wn + (nt << 3) + (tig << 1);
            float2 bz = *(const float2*)(bias + col);
            float2 o0, o1;
            o0.x = acc[mt][nt][0] + bz.x; o0.y = acc[mt][nt][1] + bz.y;
            o1.x = acc[mt][nt][2] + bz.x; o1.y = acc[mt][nt][3] + bz.y;
            if (ROUND) {
                o0.x = __uint_as_float(f2tf32(o0.x));
                o0.y = __uint_as_float(f2tf32(o0.y));
                o1.x = __uint_as_float(f2tf32(o1.x));
                o1.y = __uint_as_float(f2tf32(o1.y));
            }
            *(float2*)(C + (size_t)row * N + col)       = o0;
            *(float2*)(C + (size_t)(row + 8) * N + col) = o1;
        }
    }
}

// ---------------------------------------------------------------------------
// Banded flash attention, tf32 tensor cores + fp32 softmax.
// qkv is pre-rounded tf32 -> fragment loads are raw bit reinterprets.
// cp.async double-buffered K/V tiles (dynamic smem), 1 sync per tile.
// Output y written tf32-rounded (feeds GEMM2 directly).
// ---------------------------------------------------------------------------
#define KPAD 68
#define VPAD 72
#define KS_ELE (64 * KPAD)
#define VS_ELE (64 * VPAD)
#define ATTN_SMEM ((2 * KS_ELE + 2 * VS_ELE) * 4)

__global__ __launch_bounds__(128)
void attn_tc(const float* __restrict__ qkv, float* __restrict__ yout)
{
    extern __shared__ float sm[];
    float* Kb0 = sm;
    float* Kb1 = sm + KS_ELE;
    float* Vb0 = sm + 2 * KS_ELE;
    float* Vb1 = sm + 2 * KS_ELE + VS_ELE;

    int tid  = threadIdx.x;
    int wid  = tid >> 5, lane = tid & 31;
    int gro  = lane >> 2, tig = lane & 3;
    int i0   = blockIdx.x << 6;
    int h    = blockIdx.y, b = blockIdx.z;
    int baseq = h << 6;
    int wrow = wid << 4;
    int ir0 = i0 + wrow + gro;
    int ir1 = ir0 + 8;

    // staging decomposition (per stage: K 1024 chunks + V 1024 chunks, 8+8/thread)
    int srow = tid >> 4;          // + it*8
    int scol = (tid & 15) << 2;

    // ---- Q fragments (raw tf32 bits, once per block) ----
    const float* qp = qkv + ((size_t)(b * T_SEQ + i0 + wrow)) * 3072 + baseq;
    unsigned qf[8][4];
#pragma unroll
    for (int kt = 0; kt < 8; kt++) {
        int kc = (kt << 3) + tig;
        qf[kt][0] = __float_as_uint(qp[gro * 3072 + kc]);
        qf[kt][1] = __float_as_uint(qp[(gro + 8) * 3072 + kc]);
        qf[kt][2] = __float_as_uint(qp[gro * 3072 + kc + 4]);
        qf[kt][3] = __float_as_uint(qp[(gro + 8) * 3072 + kc + 4]);
    }

    float m0 = -1e30f, m1 = -1e30f, l0 = 0.f, l1 = 0.f;
    float oreg[8][4];
#pragma unroll
    for (int nt = 0; nt < 8; nt++)
#pragma unroll
        for (int e = 0; e < 4; e++) oreg[nt][e] = 0.f;

    int cutoff = g_cutoff[h];
    int t0 = i0 - cutoff + 1;
    int jstart = (t0 <= 0) ? 0 : (t0 & ~63);
    const float* maskh = g_mask + h * T_SEQ;

    int srcA = (lane & ~3) | (tig >> 1);
    int srcB = srcA + 2;
    bool odd = (tig & 1);

    // prefetch first tile into stage 0
    {
        const float* base = qkv + ((size_t)(b * T_SEQ + jstart)) * 3072 + baseq;
#pragma unroll
        for (int it = 0; it < 8; it++) {
            int row = srow + (it << 3);
            const float* rp = base + (size_t)row * 3072 + scol;
            cp16(&Kb0[row * KPAD + scol], rp + 1024);
            cp16(&Vb0[row * VPAD + scol], rp + 2048);
        }
        cp_commit();
    }

    int buf = 0;
    for (int j0 = jstart; j0 <= i0; j0 += 64) {
        cp_wait0();
        __syncthreads();
        if (j0 + 64 <= i0) {
            float* Kn = buf ? Kb0 : Kb1;
            float* Vn = buf ? Vb0 : Vb1;
            const float* base = qkv + ((size_t)(b * T_SEQ + j0 + 64)) * 3072 + baseq;
#pragma unroll
            for (int it = 0; it < 8; it++) {
                int row = srow + (it << 3);
                const float* rp = base + (size_t)row * 3072 + scol;
                cp16(&Kn[row * KPAD + scol], rp + 1024);
                cp16(&Vn[row * VPAD + scol], rp + 2048);
            }
            cp_commit();
        }
        const float* Kc = buf ? Kb1 : Kb0;
        const float* Vc = buf ? Vb1 : Vb0;

        // ---- S = Q K^T (16x64 per warp) ----
        float sreg[8][4];
#pragma unroll
        for (int nt = 0; nt < 8; nt++) {
#pragma unroll
            for (int e = 0; e < 4; e++) sreg[nt][e] = 0.f;
            int jb = (nt << 3) + gro;
#pragma unroll
            for (int kt = 0; kt < 8; kt++) {
                unsigned b0 = __float_as_uint(Kc[jb * KPAD + (kt << 3) + tig]);
                unsigned b1 = __float_as_uint(Kc[jb * KPAD + (kt << 3) + tig + 4]);
                mma_tf32(sreg[nt], qf[kt][0], qf[kt][1], qf[kt][2], qf[kt][3], b0, b1);
            }
        }

        // ---- online softmax ----
        float vm0 = -1e30f, vm1 = -1e30f;
#pragma unroll
        for (int nt = 0; nt < 8; nt++) {
            int jn = j0 + (nt << 3) + (tig << 1);
            float s0 = (jn     <= ir0) ? sreg[nt][0] * 0.125f : -1e30f;
            float s1 = (jn + 1 <= ir0) ? sreg[nt][1] * 0.125f : -1e30f;
            float s2 = (jn     <= ir1) ? sreg[nt][2] * 0.125f : -1e30f;
            float s3 = (jn + 1 <= ir1) ? sreg[nt][3] * 0.125f : -1e30f;
            sreg[nt][0] = s0; sreg[nt][1] = s1; sreg[nt][2] = s2; sreg[nt][3] = s3;
            vm0 = fmaxf(vm0, fmaxf(s0, s1));
            vm1 = fmaxf(vm1, fmaxf(s2, s3));
        }
        vm0 = fmaxf(vm0, __shfl_xor_sync(0xffffffffu, vm0, 1));
        vm0 = fmaxf(vm0, __shfl_xor_sync(0xffffffffu, vm0, 2));
        vm1 = fmaxf(vm1, __shfl_xor_sync(0xffffffffu, vm1, 1));
        vm1 = fmaxf(vm1, __shfl_xor_sync(0xffffffffu, vm1, 2));
        float mn0 = fmaxf(m0, vm0), mn1 = fmaxf(m1, vm1);
        float f0 = __expf(m0 - mn0), f1 = __expf(m1 - mn1);
        float rs0 = 0.f, rs1 = 0.f;
#pragma unroll
        for (int nt = 0; nt < 8; nt++) {
            int jn = j0 + (nt << 3) + (tig << 1);
            float p0 = 0.f, p1 = 0.f, p2 = 0.f, p3 = 0.f;
            if (jn <= ir0) {
                int r = ir0 - jn; if (r > 2047) r = 2047;
                p0 = __expf(sreg[nt][0] - mn0) * __ldg(maskh + r);
            }
            if (jn + 1 <= ir0) {
                int r = ir0 - jn - 1; if (r > 2047) r = 2047;
                p1 = __expf(sreg[nt][1] - mn0) * __ldg(maskh + r);
            }
            if (jn <= ir1) {
                int r = ir1 - jn; if (r > 2047) r = 2047;
                p2 = __expf(sreg[nt][2] - mn1) * __ldg(maskh + r);
            }
            if (jn + 1 <= ir1) {
                int r = ir1 - jn - 1; if (r > 2047) r = 2047;
                p3 = __expf(sreg[nt][3] - mn1) * __ldg(maskh + r);
            }
            sreg[nt][0] = p0; sreg[nt][1] = p1; sreg[nt][2] = p2; sreg[nt][3] = p3;
            rs0 += p0 + p1; rs1 += p2 + p3;
        }
        rs0 += __shfl_xor_sync(0xffffffffu, rs0, 1);
        rs0 += __shfl_xor_sync(0xffffffffu, rs0, 2);
        rs1 += __shfl_xor_sync(0xffffffffu, rs1, 1);
        rs1 += __shfl_xor_sync(0xffffffffu, rs1, 2);
        l0 = l0 * f0 + rs0; m0 = mn0;
        l1 = l1 * f1 + rs1; m1 = mn1;
#pragma unroll
        for (int nt = 0; nt < 8; nt++) {
            oreg[nt][0] *= f0; oreg[nt][1] *= f0;
            oreg[nt][2] *= f1; oreg[nt][3] *= f1;
        }

        // ---- O += P V : P C-layout -> A-layout via shuffles ----
#pragma unroll
        for (int kt = 0; kt < 8; kt++) {
            float y0 = __shfl_sync(0xffffffffu, sreg[kt][0], srcA);
            float y1 = __shfl_sync(0xffffffffu, sreg[kt][1], srcA);
            float y2 = __shfl_sync(0xffffffffu, sreg[kt][2], srcA);
            float y3 = __shfl_sync(0xffffffffu, sreg[kt][3], srcA);
            float z0 = __shfl_sync(0xffffffffu, sreg[kt][0], srcB);
            float z1 = __shfl_sync(0xffffffffu, sreg[kt][1], srcB);
            float z2 = __shfl_sync(0xffffffffu, sreg[kt][2], srcB);
            float z3 = __shfl_sync(0xffffffffu, sreg[kt][3], srcB);
            unsigned a0 = f2tf32(odd ? y1 : y0);
            unsigned a1 = f2tf32(odd ? y3 : y2);
            unsigned a2 = f2tf32(odd ? z1 : z0);
            unsigned a3 = f2tf32(odd ? z3 : z2);
            int kb = kt << 3;
#pragma unroll
            for (int nt = 0; nt < 8; nt++) {
                unsigned b0 = __float_as_uint(Vc[(kb + tig) * VPAD + (nt << 3) + gro]);
                unsigned b1 = __float_as_uint(Vc[(kb + tig + 4) * VPAD + (nt << 3) + gro]);
                mma_tf32(oreg[nt], a0, a1, a2, a3, b0, b1);
            }
        }
        buf ^= 1;
    }

    // ---- epilogue (tf32-rounded: feeds GEMM2) ----
    float inv0 = 1.f / l0, inv1 = 1.f / l1;
#pragma unroll
    for (int nt = 0; nt < 8; nt++) {
        int col = baseq + (nt << 3) + (tig << 1);
        float2 o0, o1;
        o0.x = __uint_as_float(f2tf32(oreg[nt][0] * inv0));
        o0.y = __uint_as_float(f2tf32(oreg[nt][1] * inv0));
        o1.x = __uint_as_float(f2tf32(oreg[nt][2] * inv1));
        o1.y = __uint_as_float(f2tf32(oreg[nt][3] * inv1));
        *(float2*)(yout + ((size_t)(b * T_SEQ + ir0)) * 1024 + col) = o0;
        *(float2*)(yout + ((size_t)(b * T_SEQ + ir1)) * 1024 + col) = o1;
    }
}

// ---------------------------------------------------------------------------
extern "C" void kernel_launch(void* const* d_in, const int* in_sizes, int n_in,
                              void* d_out, int out_size)
{
    const float* x        = (const float*)d_in[0];
    const float* w_attn   = (const float*)d_in[1];
    const float* b_attn   = (const float*)d_in[2];
    const float* w_proj   = (const float*)d_in[3];
    const float* b_proj   = (const float*)d_in[4];
    const float* span_p   = (const float*)d_in[5];
    const float* period_w = (const float*)d_in[6];
    const float* ratio_w  = (const float*)d_in[7];
    float* out = (float*)d_out;

    void* p;
    cudaGetSymbolAddress(&p, g_qkv);  float* qkv  = (float*)p;
    cudaGetSymbolAddress(&p, g_attn); float* attn = (float*)p;
    cudaGetSymbolAddress(&p, g_xc);   float* xc   = (float*)p;
    cudaGetSymbolAddress(&p, g_wac);  float* wac  = (float*)p;
    cudaGetSymbolAddress(&p, g_wpc);  float* wpc  = (float*)p;

    cudaFuncSetAttribute(attn_tc, cudaFuncAttributeMaxDynamicSharedMemorySize, ATTN_SMEM);

    float* loss_ptr = (out_size > MTOT * C_EMB) ? out + MTOT * C_EMB : nullptr;

    prep_kernel<<<1, 256>>>(span_p, period_w, ratio_w, loss_ptr);
    cvt_tf32_k<<<(MTOT * C_EMB / 4) / 256, 256>>>((const float4*)x, (float4*)xc,
                                                  MTOT * C_EMB / 4);
    cvt_tf32_k<<<(C_EMB * 3 * C_EMB / 4) / 256, 256>>>((const float4*)w_attn, (float4*)wac,
                                                       C_EMB * 3 * C_EMB / 4);
    cvt_tf32_k<<<(C_EMB * C_EMB / 4) / 256, 256>>>((const float4*)w_proj, (float4*)wpc,
                                                   C_EMB * C_EMB / 4);
    gemm_tf32<true><<<dim3(3 * C_EMB / 128, MTOT / 128), 128>>>(xc, wac, b_attn, qkv,
                                                                MTOT, 3 * C_EMB, C_EMB);
    attn_tc<<<dim3(T_SEQ / 64, NH, 2), 128, ATTN_SMEM>>>(qkv, attn);
    gemm_tf32<false><<<dim3(C_EMB / 128, MTOT / 128), 128>>>(attn, wpc, b_proj, out,
                                                             MTOT, C_EMB, C_EMB);
}